// round 2
// baseline (speedup 1.0000x reference)
#include <cuda_runtime.h>

#define BB 32
#define TT 1024
#define RR 8
#define CC 32
#define NPRD 128
#define RCDIM 256
#define HIDD 1024
#define NLAT 160
#define RKEEP 6
#define KSPLIT 8

// scratch (no allocations allowed)
__device__ float g_M[NLAT * RCDIM];           // M = V_W @ U_W (tf32-rounded)
__device__ float g_Mp[KSPLIT][NLAT * RCDIM];  // K-split partials
__device__ float g_Wtf[RR * CC * NPRD];       // tf32-rounded W_area
__device__ float g_biasb[BB * NLAT];          // per-batch fused bias

__device__ __forceinline__ unsigned f2tf(float x) {
    unsigned r;
    asm("cvt.rna.tf32.f32 %0, %1;" : "=r"(r) : "f"(x));
    return r;
}

__device__ __forceinline__ void mma8(float* c,
                                     unsigned a0, unsigned a1, unsigned a2, unsigned a3,
                                     unsigned b0, unsigned b1) {
    asm volatile(
        "mma.sync.aligned.m16n8k8.row.col.f32.tf32.tf32.f32 "
        "{%0,%1,%2,%3}, {%4,%5,%6,%7}, {%8,%9}, {%0,%1,%2,%3};"
        : "+f"(c[0]), "+f"(c[1]), "+f"(c[2]), "+f"(c[3])
        : "r"(a0), "r"(a1), "r"(a2), "r"(a3), "r"(b0), "r"(b1));
}

__device__ __forceinline__ void cp16(float* dst, const float4* src) {
    unsigned d = (unsigned)__cvta_generic_to_shared(dst);
    asm volatile("cp.async.cg.shared.global [%0], [%1], 16;\n"
                 :: "r"(d), "l"(src) : "memory");
}

// ---------------------------------------------------------------------------
// p1a: M partials. grid = 5(l,32) x 4(c,64) x 8(kc,128) = 160 blocks, 256 thr.
// Register-tiled 2x4 per thread, float4 B loads.
// ---------------------------------------------------------------------------
__global__ void __launch_bounds__(256) p1a_kernel(const float* __restrict__ V_W,
                                                  const float* __restrict__ U_W) {
    __shared__ float Vs[32 * 132];
    __shared__ float Us[128 * 68];
    const int bx = blockIdx.x;
    const int kc = bx & 7;
    const int ctile = (bx >> 3) & 3;
    const int ltile = bx >> 5;
    const int tid = threadIdx.x;

    // Vs: 32 rows (l) x 128 (k)
#pragma unroll
    for (int k = 0; k < 4; k++) {
        const int idx = tid + k * 256;
        const int row = idx >> 5, c4 = idx & 31;
        *(float4*)(Vs + row * 132 + c4 * 4) =
            *(const float4*)(V_W + (size_t)(ltile * 32 + row) * HIDD + kc * 128 + c4 * 4);
    }
    // Us: 128 rows (k) x 64 (c)
#pragma unroll
    for (int k = 0; k < 8; k++) {
        const int idx = tid + k * 256;
        const int row = idx >> 4, c4 = idx & 15;
        *(float4*)(Us + row * 68 + c4 * 4) =
            *(const float4*)(U_W + (size_t)(kc * 128 + row) * RCDIM + ctile * 64 + c4 * 4);
    }
    __syncthreads();

    const int ty = tid >> 4, tx = tid & 15;
    float acc[2][4] = {};
#pragma unroll 16
    for (int k = 0; k < 128; k++) {
        const float a0 = Vs[(ty * 2) * 132 + k];
        const float a1 = Vs[(ty * 2 + 1) * 132 + k];
        const float4 bv = *(const float4*)(Us + k * 68 + tx * 4);
        acc[0][0] += a0 * bv.x; acc[0][1] += a0 * bv.y;
        acc[0][2] += a0 * bv.z; acc[0][3] += a0 * bv.w;
        acc[1][0] += a1 * bv.x; acc[1][1] += a1 * bv.y;
        acc[1][2] += a1 * bv.z; acc[1][3] += a1 * bv.w;
    }
#pragma unroll
    for (int rr = 0; rr < 2; rr++) {
        *(float4*)(&g_Mp[kc][(size_t)(ltile * 32 + ty * 2 + rr) * RCDIM + ctile * 64 + tx * 4]) =
            make_float4(acc[rr][0], acc[rr][1], acc[rr][2], acc[rr][3]);
    }
}

// ---------------------------------------------------------------------------
// p1b: reduce partials -> g_M (tf32-rounded); also pre-round W_area -> g_Wtf.
// grid 160 x 256
// ---------------------------------------------------------------------------
__global__ void __launch_bounds__(256) p1b_kernel(const float* __restrict__ W_area) {
    const int idx = blockIdx.x * 256 + threadIdx.x;  // < 40960
    float s = 0.f;
#pragma unroll
    for (int p = 0; p < KSPLIT; p++) s += g_Mp[p][idx];
    g_M[idx] = __uint_as_float(f2tf(s));
    if (idx < RR * CC * NPRD) g_Wtf[idx] = __uint_as_float(f2tf(W_area[idx]));
}

// ---------------------------------------------------------------------------
// p2: bias2[l] = V_W[l]·U_b + V_b[l];
//     biasb[b][l] = bias2[l] + sum_{kept r,c} g_M[l][32r+c] * b_area[r][c]
// ---------------------------------------------------------------------------
__global__ void __launch_bounds__(128) p2_kernel(const float* __restrict__ V_W,
                                                 const float* __restrict__ U_b,
                                                 const float* __restrict__ V_b,
                                                 const float* __restrict__ b_area,
                                                 const int* __restrict__ ids) {
    __shared__ float red[128];
    const int l = blockIdx.x, tid = threadIdx.x;
    float s = 0.f;
    for (int i = tid; i < HIDD; i += 128) s += V_W[(size_t)l * HIDD + i] * U_b[i];
    red[tid] = s;
    __syncthreads();
    for (int st = 64; st > 0; st >>= 1) {
        if (tid < st) red[tid] += red[tid + st];
        __syncthreads();
    }
    const float bias2 = red[0] + V_b[l];
    if (tid < BB) {
        const int b = tid;
        float s2 = bias2;
#pragma unroll
        for (int j = 0; j < RKEEP; j++) {
            const int r = ids[b * RR + j];
            const float* Mrow = g_M + (size_t)l * RCDIM + r * CC;
            const float* ba = b_area + r * CC;
#pragma unroll
            for (int c = 0; c < CC; c++) s2 += Mrow[c] * ba[c];
        }
        g_biasb[b * NLAT + l] = s2;
    }
}

// ---------------------------------------------------------------------------
// Main fused kernel. grid = (8 t-tiles x 32 batches), 512 threads, 1 CTA/SM.
// cp.async double-buffered x and W tiles per kept region; M via LDG/L1.
// ---------------------------------------------------------------------------
constexpr int XS = 132;            // row stride (floats); 132%32==4 conflict-free
constexpr int HS = 36;
constexpr int XBUF = 128 * XS;     // 16896 floats
constexpr int WBUF = 32 * XS;      // 4224
constexpr int W_OFF = 2 * XBUF;    // 33792
constexpr int H_OFF = W_OFF + 2 * WBUF;  // 42240
constexpr int B_OFF = H_OFF + 128 * HS;  // 46848
constexpr int SMEM_FLOATS = B_OFF + NLAT;
constexpr int SMEM_BYTES = SMEM_FLOATS * 4;  // 188,032 B

__global__ void __launch_bounds__(512, 1) main_kernel(const float* __restrict__ spikes,
                                                      const int* __restrict__ ids,
                                                      float* __restrict__ out) {
    extern __shared__ float sm[];
    float* xs = sm;
    float* ws = sm + W_OFF;
    float* hs = sm + H_OFF;
    float* bias_s = sm + B_OFF;

    const int tid = threadIdx.x;
    const int wid = tid >> 5, lane = tid & 31;
    const int g = lane >> 2, tig = lane & 3;
    const int b = blockIdx.y, t0 = blockIdx.x * 128;

    if (tid < NLAT) bias_s[tid] = g_biasb[b * NLAT + tid];

    const size_t xbase = ((size_t)b * TT + t0) * (size_t)(RR * NPRD);

    // stage1: 8 m-tiles(16) x 2 n-halves(16); stage2: 4 m-groups(32) x 4 n-groups(40)
    const int mt = wid >> 1, nh = wid & 1;
    const int mg = wid >> 2, ng = wid & 3;

    float acc[2][5][4];
#pragma unroll
    for (int a = 0; a < 2; a++)
#pragma unroll
        for (int n = 0; n < 5; n++)
#pragma unroll
            for (int q = 0; q < 4; q++) acc[a][n][q] = 0.f;

    auto prefetch = [&](int buf, int r) {
        const float4* xg = (const float4*)(spikes + xbase + (size_t)r * NPRD);
        float* xd = xs + buf * XBUF;
#pragma unroll
        for (int k = 0; k < 8; k++) {
            const int idx = tid + k * 512;
            const int row = idx >> 5, c4 = idx & 31;
            cp16(xd + row * XS + c4 * 4, xg + (size_t)row * 256 + c4);
        }
        const float4* wg = (const float4*)(g_Wtf + (size_t)r * CC * NPRD);
        float* wd = ws + buf * WBUF;
#pragma unroll
        for (int k = 0; k < 2; k++) {
            const int idx = tid + k * 512;
            const int row = idx >> 5, c4 = idx & 31;
            cp16(wd + row * XS + c4 * 4, wg + row * 32 + c4);
        }
    };

    prefetch(0, __ldg(ids + b * RR));
    asm volatile("cp.async.commit_group;\n" ::: "memory");

    for (int j = 0; j < RKEEP; j++) {
        const int cur = j & 1;
        if (j + 1 < RKEEP) {
            prefetch(cur ^ 1, __ldg(ids + b * RR + j + 1));
            asm volatile("cp.async.commit_group;\n" ::: "memory");
            asm volatile("cp.async.wait_group 1;\n" ::: "memory");
        } else {
            asm volatile("cp.async.wait_group 0;\n" ::: "memory");
        }
        __syncthreads();

        const int r = __ldg(ids + b * RR + j);

        // ---- stage 1: h(128x32) = x(128x128) @ W^T (K=128, W pre-rounded) ----
        float hacc[2][4];
#pragma unroll
        for (int n = 0; n < 2; n++)
#pragma unroll
            for (int q = 0; q < 4; q++) hacc[n][q] = 0.f;
        {
            const float* xa = xs + cur * XBUF + mt * 16 * XS;
            const float* wa = ws + cur * WBUF;
#pragma unroll
            for (int ks = 0; ks < 16; ks++) {
                const float* xp = xa + ks * 8;
                const unsigned a0 = f2tf(xp[g * XS + tig]);
                const unsigned a1 = f2tf(xp[(g + 8) * XS + tig]);
                const unsigned a2 = f2tf(xp[g * XS + tig + 4]);
                const unsigned a3 = f2tf(xp[(g + 8) * XS + tig + 4]);
#pragma unroll
                for (int nt = 0; nt < 2; nt++) {
                    const float* wp = wa + (nh * 16 + nt * 8 + g) * XS + ks * 8;
                    mma8(hacc[nt], a0, a1, a2, a3,
                         __float_as_uint(wp[tig]), __float_as_uint(wp[tig + 4]));
                }
            }
        }
        // store h (pre-rounded tf32)
#pragma unroll
        for (int nt = 0; nt < 2; nt++) {
            const int col = nh * 16 + nt * 8 + 2 * tig;
            float* hp0 = hs + (mt * 16 + g) * HS + col;
            hp0[0] = __uint_as_float(f2tf(hacc[nt][0]));
            hp0[1] = __uint_as_float(f2tf(hacc[nt][1]));
            float* hp1 = hs + (mt * 16 + g + 8) * HS + col;
            hp1[0] = __uint_as_float(f2tf(hacc[nt][2]));
            hp1[1] = __uint_as_float(f2tf(hacc[nt][3]));
        }
        __syncthreads();

        // ---- stage 2: out(128x160) += h @ M_r^T (K=32, M pre-rounded, via L1) ----
        const float* Mr = g_M + (size_t)r * CC;
#pragma unroll
        for (int ks = 0; ks < 4; ks++) {
            unsigned A[2][4];
#pragma unroll
            for (int m2 = 0; m2 < 2; m2++) {
                const float* hp = hs + (mg * 32 + m2 * 16) * HS + ks * 8;
                A[m2][0] = __float_as_uint(hp[g * HS + tig]);
                A[m2][1] = __float_as_uint(hp[(g + 8) * HS + tig]);
                A[m2][2] = __float_as_uint(hp[g * HS + tig + 4]);
                A[m2][3] = __float_as_uint(hp[(g + 8) * HS + tig + 4]);
            }
#pragma unroll
            for (int nt = 0; nt < 5; nt++) {
                const float* mp = Mr + (size_t)(ng * 40 + nt * 8 + g) * RCDIM + ks * 8;
                const unsigned b0 = __float_as_uint(__ldg(mp + tig));
                const unsigned b1 = __float_as_uint(__ldg(mp + tig + 4));
                mma8(acc[0][nt], A[0][0], A[0][1], A[0][2], A[0][3], b0, b1);
                mma8(acc[1][nt], A[1][0], A[1][1], A[1][2], A[1][3], b0, b1);
            }
        }
        __syncthreads();
    }

    // ---- epilogue ----
    float* og = out + ((size_t)b * TT + t0) * NLAT;
#pragma unroll
    for (int m2 = 0; m2 < 2; m2++) {
        const int row0 = mg * 32 + m2 * 16 + g;
#pragma unroll
        for (int nt = 0; nt < 5; nt++) {
            const int col = ng * 40 + nt * 8 + 2 * tig;
            const float blo = bias_s[col], bhi = bias_s[col + 1];
            float2 v0 = make_float2(acc[m2][nt][0] + blo, acc[m2][nt][1] + bhi);
            *(float2*)(og + (size_t)row0 * NLAT + col) = v0;
            float2 v1 = make_float2(acc[m2][nt][2] + blo, acc[m2][nt][3] + bhi);
            *(float2*)(og + (size_t)(row0 + 8) * NLAT + col) = v1;
        }
    }
}

extern "C" void kernel_launch(void* const* d_in, const int* in_sizes, int n_in,
                              void* d_out, int out_size) {
    const float* spikes = (const float*)d_in[0];
    const float* W_area = (const float*)d_in[1];
    const float* b_area = (const float*)d_in[2];
    const float* U_W    = (const float*)d_in[3];
    const float* U_b    = (const float*)d_in[4];
    const float* V_W    = (const float*)d_in[5];
    const float* V_b    = (const float*)d_in[6];
    const int*   ids    = (const int*)d_in[7];
    float* out = (float*)d_out;

    cudaFuncSetAttribute(main_kernel, cudaFuncAttributeMaxDynamicSharedMemorySize, SMEM_BYTES);

    p1a_kernel<<<160, 256>>>(V_W, U_W);
    p1b_kernel<<<160, 256>>>(W_area);
    p2_kernel<<<160, 128>>>(V_W, U_b, V_b, b_area, ids);
    main_kernel<<<dim3(8, 32), 512, SMEM_BYTES>>>(spikes, ids, out);
}

// round 3
// speedup vs baseline: 1.0142x; 1.0142x over previous
#include <cuda_runtime.h>

#define BB 32
#define TT 1024
#define RR 8
#define CC 32
#define NPRD 128
#define RCDIM 256
#define HIDD 1024
#define NLAT 160
#define RKEEP 6
#define KSPLIT 8

// scratch (no allocations allowed)
__device__ float g_M[NLAT * RCDIM];           // M = V_W @ U_W (tf32-rounded)
__device__ float g_Mp[KSPLIT][NLAT * RCDIM];  // K-split partials
__device__ float g_Wtf[RR * CC * NPRD];       // tf32-rounded W_area
__device__ float g_biasb[BB * NLAT];          // per-batch fused bias

__device__ __forceinline__ unsigned f2tf(float x) {
    unsigned r;
    asm("cvt.rna.tf32.f32 %0, %1;" : "=r"(r) : "f"(x));
    return r;
}

__device__ __forceinline__ void mma8(float* c,
                                     unsigned a0, unsigned a1, unsigned a2, unsigned a3,
                                     unsigned b0, unsigned b1) {
    asm volatile(
        "mma.sync.aligned.m16n8k8.row.col.f32.tf32.tf32.f32 "
        "{%0,%1,%2,%3}, {%4,%5,%6,%7}, {%8,%9}, {%0,%1,%2,%3};"
        : "+f"(c[0]), "+f"(c[1]), "+f"(c[2]), "+f"(c[3])
        : "r"(a0), "r"(a1), "r"(a2), "r"(a3), "r"(b0), "r"(b1));
}

__device__ __forceinline__ void cp16(float* dst, const float4* src) {
    unsigned d = (unsigned)__cvta_generic_to_shared(dst);
    asm volatile("cp.async.cg.shared.global [%0], [%1], 16;\n"
                 :: "r"(d), "l"(src) : "memory");
}

// ---------------------------------------------------------------------------
// p1a: M partials. grid = 5(l,32) x 4(c,64) x 8(kc,128) = 160 blocks, 256 thr.
// ---------------------------------------------------------------------------
__global__ void __launch_bounds__(256) p1a_kernel(const float* __restrict__ V_W,
                                                  const float* __restrict__ U_W) {
    __shared__ float Vs[32 * 132];
    __shared__ float Us[128 * 68];
    const int bx = blockIdx.x;
    const int kc = bx & 7;
    const int ctile = (bx >> 3) & 3;
    const int ltile = bx >> 5;
    const int tid = threadIdx.x;

#pragma unroll
    for (int k = 0; k < 4; k++) {
        const int idx = tid + k * 256;
        const int row = idx >> 5, c4 = idx & 31;
        *(float4*)(Vs + row * 132 + c4 * 4) =
            *(const float4*)(V_W + (size_t)(ltile * 32 + row) * HIDD + kc * 128 + c4 * 4);
    }
#pragma unroll
    for (int k = 0; k < 8; k++) {
        const int idx = tid + k * 256;
        const int row = idx >> 4, c4 = idx & 15;
        *(float4*)(Us + row * 68 + c4 * 4) =
            *(const float4*)(U_W + (size_t)(kc * 128 + row) * RCDIM + ctile * 64 + c4 * 4);
    }
    __syncthreads();

    const int ty = tid >> 4, tx = tid & 15;
    float acc[2][4] = {};
#pragma unroll 16
    for (int k = 0; k < 128; k++) {
        const float a0 = Vs[(ty * 2) * 132 + k];
        const float a1 = Vs[(ty * 2 + 1) * 132 + k];
        const float4 bv = *(const float4*)(Us + k * 68 + tx * 4);
        acc[0][0] += a0 * bv.x; acc[0][1] += a0 * bv.y;
        acc[0][2] += a0 * bv.z; acc[0][3] += a0 * bv.w;
        acc[1][0] += a1 * bv.x; acc[1][1] += a1 * bv.y;
        acc[1][2] += a1 * bv.z; acc[1][3] += a1 * bv.w;
    }
#pragma unroll
    for (int rr = 0; rr < 2; rr++) {
        *(float4*)(&g_Mp[kc][(size_t)(ltile * 32 + ty * 2 + rr) * RCDIM + ctile * 64 + tx * 4]) =
            make_float4(acc[rr][0], acc[rr][1], acc[rr][2], acc[rr][3]);
    }
}

// ---------------------------------------------------------------------------
// p1b: reduce partials -> g_M (tf32-rounded); pre-round W_area -> g_Wtf.
// ---------------------------------------------------------------------------
__global__ void __launch_bounds__(256) p1b_kernel(const float* __restrict__ W_area) {
    const int idx = blockIdx.x * 256 + threadIdx.x;  // < 40960
    float s = 0.f;
#pragma unroll
    for (int p = 0; p < KSPLIT; p++) s += g_Mp[p][idx];
    g_M[idx] = __uint_as_float(f2tf(s));
    if (idx < RR * CC * NPRD) g_Wtf[idx] = __uint_as_float(f2tf(W_area[idx]));
}

// ---------------------------------------------------------------------------
// p2: biasb[b][l] = V_W[l]·U_b + V_b[l] + sum_{kept r,c} g_M[l][32r+c]*b_area[r][c]
// ---------------------------------------------------------------------------
__global__ void __launch_bounds__(128) p2_kernel(const float* __restrict__ V_W,
                                                 const float* __restrict__ U_b,
                                                 const float* __restrict__ V_b,
                                                 const float* __restrict__ b_area,
                                                 const int* __restrict__ ids) {
    __shared__ float red[128];
    const int l = blockIdx.x, tid = threadIdx.x;
    float s = 0.f;
    for (int i = tid; i < HIDD; i += 128) s += V_W[(size_t)l * HIDD + i] * U_b[i];
    red[tid] = s;
    __syncthreads();
    for (int st = 64; st > 0; st >>= 1) {
        if (tid < st) red[tid] += red[tid + st];
        __syncthreads();
    }
    const float bias2 = red[0] + V_b[l];
    if (tid < BB) {
        const int b = tid;
        float s2 = bias2;
#pragma unroll
        for (int j = 0; j < RKEEP; j++) {
            const int r = ids[b * RR + j];
            const float* Mrow = g_M + (size_t)l * RCDIM + r * CC;
            const float* ba = b_area + r * CC;
#pragma unroll
            for (int c = 0; c < CC; c++) s2 += Mrow[c] * ba[c];
        }
        g_biasb[b * NLAT + l] = s2;
    }
}

// ---------------------------------------------------------------------------
// Main fused kernel. grid = (16 t-tiles x 32 batches), 256 threads,
// 2 CTAs/SM (smem 111 KB/CTA). TILE_T = 64 rows.
// Per kept region r:
//   stage1: h(64x32)  = x(64x128) @ Wtf[r]^T   (smem, double-buffered cp.async)
//   stage2: out(64x160) += h @ M_r^T  (M frags prefetched to regs before stage1)
// ---------------------------------------------------------------------------
constexpr int TILE_T = 64;
constexpr int XS = 132;             // 132 % 32 == 4 -> conflict-free frag LDS
constexpr int HS = 36;
constexpr int XBUF = TILE_T * XS;   // 8448 floats
constexpr int WBUF = 32 * XS;       // 4224
constexpr int W_OFF = 2 * XBUF;                 // 16896
constexpr int H_OFF = W_OFF + 2 * WBUF;         // 25344
constexpr int B_OFF = H_OFF + TILE_T * HS;      // 27648
constexpr int SMEM_FLOATS = B_OFF + NLAT;       // 27808
constexpr int SMEM_BYTES = SMEM_FLOATS * 4;     // 111,232 B

__global__ void __launch_bounds__(256, 2) main_kernel(const float* __restrict__ spikes,
                                                      const int* __restrict__ ids,
                                                      float* __restrict__ out) {
    extern __shared__ float sm[];
    float* xs = sm;
    float* ws = sm + W_OFF;
    float* hs = sm + H_OFF;
    float* bias_s = sm + B_OFF;

    const int tid = threadIdx.x;
    const int wid = tid >> 5, lane = tid & 31;
    const int g = lane >> 2, tig = lane & 3;
    const int b = blockIdx.y, t0 = blockIdx.x * TILE_T;

    if (tid < NLAT) bias_s[tid] = g_biasb[b * NLAT + tid];

    const size_t xbase = ((size_t)b * TT + t0) * (size_t)(RR * NPRD);

    // stage1: 4 m-tiles(16 rows) x 2 n-halves(16 cols)
    const int mt = wid >> 1, nh = wid & 1;
    // stage2: 2 m-groups(32 rows) x 4 n-groups(40 cols)
    const int mg = wid >> 2, ng = wid & 3;

    int kept[RKEEP];
#pragma unroll
    for (int j = 0; j < RKEEP; j++) kept[j] = __ldg(ids + b * RR + j);

    float acc[2][5][4];
#pragma unroll
    for (int a = 0; a < 2; a++)
#pragma unroll
        for (int n = 0; n < 5; n++)
#pragma unroll
            for (int q = 0; q < 4; q++) acc[a][n][q] = 0.f;

    auto prefetch = [&](int buf, int r) {
        const float4* xg = (const float4*)(spikes + xbase + (size_t)r * NPRD);
        float* xd = xs + buf * XBUF;
#pragma unroll
        for (int k = 0; k < 8; k++) {           // 64 rows x 32 float4
            const int idx = tid + k * 256;
            const int row = idx >> 5, c4 = idx & 31;
            cp16(xd + row * XS + c4 * 4, xg + (size_t)row * 256 + c4);
        }
        const float4* wg = (const float4*)(g_Wtf + (size_t)r * CC * NPRD);
        float* wd = ws + buf * WBUF;
#pragma unroll
        for (int k = 0; k < 4; k++) {           // 32 rows x 32 float4
            const int idx = tid + k * 256;
            const int row = idx >> 5, c4 = idx & 31;
            cp16(wd + row * XS + c4 * 4, wg + row * 32 + c4);
        }
    };

    prefetch(0, kept[0]);
    asm volatile("cp.async.commit_group;\n" ::: "memory");

    for (int j = 0; j < RKEEP; j++) {
        const int cur = j & 1;
        const int r = kept[j];

        // ---- prefetch stage-2 B fragments (g_M slice) into registers NOW,
        //      so the L2 round-trip overlaps the whole stage-1 MMA loop ----
        unsigned Bf[4][5][2];
        {
            const float* Mr = g_M + (size_t)r * CC;
#pragma unroll
            for (int ks = 0; ks < 4; ks++)
#pragma unroll
                for (int nt = 0; nt < 5; nt++) {
                    const float* mp = Mr + (size_t)(ng * 40 + nt * 8 + g) * RCDIM + ks * 8;
                    Bf[ks][nt][0] = __float_as_uint(__ldg(mp + tig));
                    Bf[ks][nt][1] = __float_as_uint(__ldg(mp + tig + 4));
                }
        }

        if (j + 1 < RKEEP) {
            prefetch(cur ^ 1, kept[j + 1]);
            asm volatile("cp.async.commit_group;\n" ::: "memory");
            asm volatile("cp.async.wait_group 1;\n" ::: "memory");
        } else {
            asm volatile("cp.async.wait_group 0;\n" ::: "memory");
        }
        __syncthreads();

        // ---- stage 1: h(64x32) = x(64x128) @ W^T, K=128 ----
        float hacc[2][4];
#pragma unroll
        for (int n = 0; n < 2; n++)
#pragma unroll
            for (int q = 0; q < 4; q++) hacc[n][q] = 0.f;
        {
            const float* xa = xs + cur * XBUF + mt * 16 * XS;
            const float* wa = ws + cur * WBUF;
#pragma unroll
            for (int ks = 0; ks < 16; ks++) {
                const float* xp = xa + ks * 8;
                const unsigned a0 = f2tf(xp[g * XS + tig]);
                const unsigned a1 = f2tf(xp[(g + 8) * XS + tig]);
                const unsigned a2 = f2tf(xp[g * XS + tig + 4]);
                const unsigned a3 = f2tf(xp[(g + 8) * XS + tig + 4]);
#pragma unroll
                for (int nt = 0; nt < 2; nt++) {
                    const float* wp = wa + (nh * 16 + nt * 8 + g) * XS + ks * 8;
                    mma8(hacc[nt], a0, a1, a2, a3,
                         __float_as_uint(wp[tig]), __float_as_uint(wp[tig + 4]));
                }
            }
        }
        // store h (pre-rounded tf32)
#pragma unroll
        for (int nt = 0; nt < 2; nt++) {
            const int col = nh * 16 + nt * 8 + 2 * tig;
            float* hp0 = hs + (mt * 16 + g) * HS + col;
            hp0[0] = __uint_as_float(f2tf(hacc[nt][0]));
            hp0[1] = __uint_as_float(f2tf(hacc[nt][1]));
            float* hp1 = hs + (mt * 16 + g + 8) * HS + col;
            hp1[0] = __uint_as_float(f2tf(hacc[nt][2]));
            hp1[1] = __uint_as_float(f2tf(hacc[nt][3]));
        }
        __syncthreads();

        // ---- stage 2: out(64x160) += h @ M_r^T, K=32, B from registers ----
#pragma unroll
        for (int ks = 0; ks < 4; ks++) {
            unsigned A[2][4];
#pragma unroll
            for (int m2 = 0; m2 < 2; m2++) {
                const float* hp = hs + (mg * 32 + m2 * 16) * HS + ks * 8;
                A[m2][0] = __float_as_uint(hp[g * HS + tig]);
                A[m2][1] = __float_as_uint(hp[(g + 8) * HS + tig]);
                A[m2][2] = __float_as_uint(hp[g * HS + tig + 4]);
                A[m2][3] = __float_as_uint(hp[(g + 8) * HS + tig + 4]);
            }
#pragma unroll
            for (int nt = 0; nt < 5; nt++) {
                mma8(acc[0][nt], A[0][0], A[0][1], A[0][2], A[0][3],
                     Bf[ks][nt][0], Bf[ks][nt][1]);
                mma8(acc[1][nt], A[1][0], A[1][1], A[1][2], A[1][3],
                     Bf[ks][nt][0], Bf[ks][nt][1]);
            }
        }
        __syncthreads();
    }

    // ---- epilogue ----
    float* og = out + ((size_t)b * TT + t0) * NLAT;
#pragma unroll
    for (int m2 = 0; m2 < 2; m2++) {
        const int row0 = mg * 32 + m2 * 16 + g;
#pragma unroll
        for (int nt = 0; nt < 5; nt++) {
            const int col = ng * 40 + nt * 8 + 2 * tig;
            const float blo = bias_s[col], bhi = bias_s[col + 1];
            float2 v0 = make_float2(acc[m2][nt][0] + blo, acc[m2][nt][1] + bhi);
            *(float2*)(og + (size_t)row0 * NLAT + col) = v0;
            float2 v1 = make_float2(acc[m2][nt][2] + blo, acc[m2][nt][3] + bhi);
            *(float2*)(og + (size_t)(row0 + 8) * NLAT + col) = v1;
        }
    }
}

extern "C" void kernel_launch(void* const* d_in, const int* in_sizes, int n_in,
                              void* d_out, int out_size) {
    const float* spikes = (const float*)d_in[0];
    const float* W_area = (const float*)d_in[1];
    const float* b_area = (const float*)d_in[2];
    const float* U_W    = (const float*)d_in[3];
    const float* U_b    = (const float*)d_in[4];
    const float* V_W    = (const float*)d_in[5];
    const float* V_b    = (const float*)d_in[6];
    const int*   ids    = (const int*)d_in[7];
    float* out = (float*)d_out;

    cudaFuncSetAttribute(main_kernel, cudaFuncAttributeMaxDynamicSharedMemorySize, SMEM_BYTES);

    p1a_kernel<<<160, 256>>>(V_W, U_W);
    p1b_kernel<<<160, 256>>>(W_area);
    p2_kernel<<<160, 128>>>(V_W, U_b, V_b, b_area, ids);
    main_kernel<<<dim3(16, 32), 256, SMEM_BYTES>>>(spikes, ids, out);
}

// round 4
// speedup vs baseline: 1.6005x; 1.5782x over previous
#include <cuda_runtime.h>

#define BB 32
#define TT 1024
#define RR 8
#define CC 32
#define NPRD 128
#define RCDIM 256
#define HIDD 1024
#define NLAT 160
#define RKEEP 6
#define KSPLIT 8

// scratch (no allocations allowed)
__device__ float g_M[NLAT * RCDIM];           // M = V_W @ U_W (tf32-rounded)
__device__ float g_Mp[KSPLIT][NLAT * RCDIM];  // K-split partials
__device__ float g_Wtf[RR * CC * NPRD];       // tf32-rounded W_area
__device__ float g_biasb[BB * NLAT];          // per-batch fused bias

__device__ __forceinline__ unsigned f2tf(float x) {
    unsigned r;
    asm("cvt.rna.tf32.f32 %0, %1;" : "=r"(r) : "f"(x));
    return r;
}

__device__ __forceinline__ void mma8(float* c,
                                     unsigned a0, unsigned a1, unsigned a2, unsigned a3,
                                     unsigned b0, unsigned b1) {
    asm volatile(
        "mma.sync.aligned.m16n8k8.row.col.f32.tf32.tf32.f32 "
        "{%0,%1,%2,%3}, {%4,%5,%6,%7}, {%8,%9}, {%0,%1,%2,%3};"
        : "+f"(c[0]), "+f"(c[1]), "+f"(c[2]), "+f"(c[3])
        : "r"(a0), "r"(a1), "r"(a2), "r"(a3), "r"(b0), "r"(b1));
}

__device__ __forceinline__ void cp16(float* dst, const float4* src) {
    unsigned d = (unsigned)__cvta_generic_to_shared(dst);
    asm volatile("cp.async.cg.shared.global [%0], [%1], 16;\n"
                 :: "r"(d), "l"(src) : "memory");
}

// ---------------------------------------------------------------------------
// p1a: M partials (register-tiled) + tf32-round W_area (160*256 == 40960).
// grid = 5(l,32) x 4(c,64) x 8(kc,128) = 160 blocks, 256 thr.
// ---------------------------------------------------------------------------
__global__ void __launch_bounds__(256) p1a_kernel(const float* __restrict__ V_W,
                                                  const float* __restrict__ U_W,
                                                  const float* __restrict__ W_area) {
    __shared__ float Vs[32 * 132];
    __shared__ float Us[128 * 68];
    const int bx = blockIdx.x;
    const int kc = bx & 7;
    const int ctile = (bx >> 3) & 3;
    const int ltile = bx >> 5;
    const int tid = threadIdx.x;

    // W rounding: one element per thread over the whole grid
    g_Wtf[bx * 256 + tid] = __uint_as_float(f2tf(W_area[bx * 256 + tid]));

#pragma unroll
    for (int k = 0; k < 4; k++) {
        const int idx = tid + k * 256;
        const int row = idx >> 5, c4 = idx & 31;
        *(float4*)(Vs + row * 132 + c4 * 4) =
            *(const float4*)(V_W + (size_t)(ltile * 32 + row) * HIDD + kc * 128 + c4 * 4);
    }
#pragma unroll
    for (int k = 0; k < 8; k++) {
        const int idx = tid + k * 256;
        const int row = idx >> 4, c4 = idx & 15;
        *(float4*)(Us + row * 68 + c4 * 4) =
            *(const float4*)(U_W + (size_t)(kc * 128 + row) * RCDIM + ctile * 64 + c4 * 4);
    }
    __syncthreads();

    const int ty = tid >> 4, tx = tid & 15;
    float acc[2][4] = {};
#pragma unroll 16
    for (int k = 0; k < 128; k++) {
        const float a0 = Vs[(ty * 2) * 132 + k];
        const float a1 = Vs[(ty * 2 + 1) * 132 + k];
        const float4 bv = *(const float4*)(Us + k * 68 + tx * 4);
        acc[0][0] += a0 * bv.x; acc[0][1] += a0 * bv.y;
        acc[0][2] += a0 * bv.z; acc[0][3] += a0 * bv.w;
        acc[1][0] += a1 * bv.x; acc[1][1] += a1 * bv.y;
        acc[1][2] += a1 * bv.z; acc[1][3] += a1 * bv.w;
    }
#pragma unroll
    for (int rr = 0; rr < 2; rr++) {
        *(float4*)(&g_Mp[kc][(size_t)(ltile * 32 + ty * 2 + rr) * RCDIM + ctile * 64 + tx * 4]) =
            make_float4(acc[rr][0], acc[rr][1], acc[rr][2], acc[rr][3]);
    }
}

// ---------------------------------------------------------------------------
// p1b: block l: (a) reduce g_Mp -> g_M row l (tf32-rounded),
//      (b) bias2[l] = V_W[l]·U_b + V_b[l],
//      (c) g_biasb[b][l] = bias2 + sum_{kept r,c} M[l][32r+c]*b_area[r][c].
// grid 160, 256 threads.
// ---------------------------------------------------------------------------
__global__ void __launch_bounds__(256) p1b_kernel(const float* __restrict__ V_W,
                                                  const float* __restrict__ U_b,
                                                  const float* __restrict__ V_b,
                                                  const float* __restrict__ b_area,
                                                  const int* __restrict__ ids) {
    __shared__ float Ms[RCDIM];
    __shared__ float ba_s[RCDIM];
    __shared__ float red[256];
    const int l = blockIdx.x, t = threadIdx.x;

    float s = 0.f;
#pragma unroll
    for (int p = 0; p < KSPLIT; p++) s += g_Mp[p][(size_t)l * RCDIM + t];
    const float mv = __uint_as_float(f2tf(s));
    g_M[(size_t)l * RCDIM + t] = mv;
    Ms[t] = mv;
    ba_s[t] = b_area[t];

    float s2 = 0.f;
#pragma unroll
    for (int i = 0; i < 4; i++)
        s2 += V_W[(size_t)l * HIDD + t + i * 256] * U_b[t + i * 256];
    red[t] = s2;
    __syncthreads();
    for (int st = 128; st > 0; st >>= 1) {
        if (t < st) red[t] += red[t + st];
        __syncthreads();
    }
    const float bias2 = red[0] + V_b[l];

    if (t < BB) {
        const int b = t;
        float s3 = bias2;
#pragma unroll
        for (int j = 0; j < RKEEP; j++) {
            const int r = ids[b * RR + j];
#pragma unroll
            for (int c = 0; c < CC; c++) s3 += Ms[r * CC + c] * ba_s[r * CC + c];
        }
        g_biasb[b * NLAT + l] = s3;
    }
}

// ---------------------------------------------------------------------------
// Main fused kernel. grid = (16 t-tiles x 32 batches), 256 threads,
// target 2 CTAs/SM. TILE_T = 64.
// Smem layouts XOR-swizzled (no padding): element (row,k) at row*128 + (k ^ 4*(row&7)).
// Pipeline per region j:  [wait xw_j] stage1 | [wait M_j] h | issue xw_{j+1} |
//                         stage2 | issue M_{j+1}
// ---------------------------------------------------------------------------
constexpr int TILE_T = 64;
constexpr int XTILE = TILE_T * 128;                 // 8192
constexpr int X_OFF = 0;                            // 2 bufs -> 16384
constexpr int W_OFF = 2 * XTILE;                    // 16384, 32*128 = 4096
constexpr int M_OFF = W_OFF + 32 * 128;             // 20480, 160*32 = 5120
constexpr int H_OFF = M_OFF + NLAT * 32;            // 25600, 64*36 = 2304
constexpr int B_OFF = H_OFF + TILE_T * 36;          // 27904
constexpr int SMEM_FLOATS = B_OFF + NLAT;           // 28064
constexpr int SMEM_BYTES = SMEM_FLOATS * 4;         // 112,256 B

__global__ void __launch_bounds__(256, 2) main_kernel(const float* __restrict__ spikes,
                                                      const int* __restrict__ ids,
                                                      float* __restrict__ out) {
    extern __shared__ float sm[];
    float* xs = sm + X_OFF;
    float* ws = sm + W_OFF;
    float* ms = sm + M_OFF;
    float* hs = sm + H_OFF;
    float* bias_s = sm + B_OFF;

    const int tid = threadIdx.x;
    const int wid = tid >> 5, lane = tid & 31;
    const int g = lane >> 2, tig = lane & 3;
    const int sw = 4 * g;
    const int b = blockIdx.y, t0 = blockIdx.x * TILE_T;

    if (tid < NLAT) bias_s[tid] = g_biasb[b * NLAT + tid];

    const size_t xbase = ((size_t)b * TT + t0) * (size_t)(RR * NPRD);

    // stage1: 4 m-tiles(16 rows) x 2 n-halves(16 cols); stage2: 2 mg x 4 ng(40 cols)
    const int mt = wid >> 1, nh = wid & 1;
    const int mg = wid >> 2, ng = wid & 3;

    int kept[RKEEP];
#pragma unroll
    for (int j = 0; j < RKEEP; j++) kept[j] = __ldg(ids + b * RR + j);

    float acc[2][5][4];
#pragma unroll
    for (int a = 0; a < 2; a++)
#pragma unroll
        for (int n = 0; n < 5; n++)
#pragma unroll
            for (int q = 0; q < 4; q++) acc[a][n][q] = 0.f;

    auto prefetch_xw = [&](int buf, int r) {
        const float4* xg = (const float4*)(spikes + xbase + (size_t)r * NPRD);
        float* xd = xs + buf * XTILE;
#pragma unroll
        for (int k = 0; k < 8; k++) {            // 64 rows x 32 float4
            const int idx = tid + k * 256;
            const int row = idx >> 5, c4 = idx & 31;
            cp16(xd + row * 128 + (c4 ^ (row & 7)) * 4, xg + (size_t)row * 256 + c4);
        }
        const float4* wg = (const float4*)(g_Wtf + (size_t)r * CC * NPRD);
#pragma unroll
        for (int k = 0; k < 4; k++) {            // 32 rows x 32 float4
            const int idx = tid + k * 256;
            const int row = idx >> 5, c4 = idx & 31;
            cp16(ws + row * 128 + (c4 ^ (row & 7)) * 4, wg + row * 32 + c4);
        }
    };
    auto prefetch_m = [&](int r) {
        const float* Mg = g_M + (size_t)r * CC;
#pragma unroll
        for (int k = 0; k < 5; k++) {            // 160 rows x 8 float4
            const int idx = tid + k * 256;
            const int row = idx >> 3, c4 = idx & 7;
            cp16(ms + row * 32 + (c4 ^ (row & 7)) * 4,
                 (const float4*)(Mg + (size_t)row * RCDIM) + c4);
        }
    };

    prefetch_xw(0, kept[0]);
    asm volatile("cp.async.commit_group;\n" ::: "memory");
    prefetch_m(kept[0]);
    asm volatile("cp.async.commit_group;\n" ::: "memory");

    for (int j = 0; j < RKEEP; j++) {
        const int cur = j & 1;

        // wait xw_j (leave M group possibly in flight)
        asm volatile("cp.async.wait_group 1;\n" ::: "memory");
        __syncthreads();

        // ---- stage 1: h(64x32) = x(64x128) @ W^T, K=128, 4 acc chains ----
        float ha[2][4] = {}, hb[2][4] = {};
        {
            const float* xr0 = xs + cur * XTILE + (mt * 16 + g) * 128;
            const float* wr0 = ws + (nh * 16 + g) * 128;
#pragma unroll
            for (int ks = 0; ks < 16; ks++) {
                const int o0 = ((ks * 8) ^ sw) + tig;
                const int o1 = o0 ^ 4;
                const unsigned a0 = f2tf(xr0[o0]);
                const unsigned a1 = f2tf(xr0[1024 + o0]);
                const unsigned a2 = f2tf(xr0[o1]);
                const unsigned a3 = f2tf(xr0[1024 + o1]);
                float* h0 = (ks & 1) ? hb[0] : ha[0];
                float* h1 = (ks & 1) ? hb[1] : ha[1];
                mma8(h0, a0, a1, a2, a3,
                     __float_as_uint(wr0[o0]), __float_as_uint(wr0[o1]));
                mma8(h1, a0, a1, a2, a3,
                     __float_as_uint(wr0[1024 + o0]), __float_as_uint(wr0[1024 + o1]));
            }
        }
        // wait M_j, then publish h (tf32-rounded)
        asm volatile("cp.async.wait_group 0;\n" ::: "memory");
#pragma unroll
        for (int nt = 0; nt < 2; nt++) {
            const int col = nh * 16 + nt * 8 + 2 * tig;
            float* hp0 = hs + (mt * 16 + g) * 36 + col;
            hp0[0] = __uint_as_float(f2tf(ha[nt][0] + hb[nt][0]));
            hp0[1] = __uint_as_float(f2tf(ha[nt][1] + hb[nt][1]));
            float* hp1 = hs + (mt * 16 + g + 8) * 36 + col;
            hp1[0] = __uint_as_float(f2tf(ha[nt][2] + hb[nt][2]));
            hp1[1] = __uint_as_float(f2tf(ha[nt][3] + hb[nt][3]));
        }
        __syncthreads();

        // x_j / w_j now dead: start next xw load (overlaps stage 2)
        if (j + 1 < RKEEP) {
            prefetch_xw(cur ^ 1, kept[j + 1]);
            asm volatile("cp.async.commit_group;\n" ::: "memory");
        }

        // ---- stage 2: out(64x160) += h @ M_r^T, K=32 ----
#pragma unroll
        for (int ks = 0; ks < 4; ks++) {
            const int o0 = ((ks * 8) ^ sw) + tig;
            const int o1 = o0 ^ 4;
            unsigned A[2][4];
#pragma unroll
            for (int m2 = 0; m2 < 2; m2++) {
                const float* hp = hs + (mg * 32 + m2 * 16) * 36 + ks * 8;
                A[m2][0] = __float_as_uint(hp[g * 36 + tig]);
                A[m2][1] = __float_as_uint(hp[(g + 8) * 36 + tig]);
                A[m2][2] = __float_as_uint(hp[g * 36 + tig + 4]);
                A[m2][3] = __float_as_uint(hp[(g + 8) * 36 + tig + 4]);
            }
#pragma unroll
            for (int nt = 0; nt < 5; nt++) {
                const float* mr = ms + (ng * 40 + nt * 8 + g) * 32;
                const unsigned b0 = __float_as_uint(mr[o0]);
                const unsigned b1 = __float_as_uint(mr[o1]);
                mma8(acc[0][nt], A[0][0], A[0][1], A[0][2], A[0][3], b0, b1);
                mma8(acc[1][nt], A[1][0], A[1][1], A[1][2], A[1][3], b0, b1);
            }
        }
        __syncthreads();

        // M_j dead: start next M load (overlaps next stage 1)
        if (j + 1 < RKEEP) {
            prefetch_m(kept[j + 1]);
            asm volatile("cp.async.commit_group;\n" ::: "memory");
        }
    }

    // ---- epilogue ----
    float* og = out + ((size_t)b * TT + t0) * NLAT;
#pragma unroll
    for (int m2 = 0; m2 < 2; m2++) {
        const int row0 = mg * 32 + m2 * 16 + g;
#pragma unroll
        for (int nt = 0; nt < 5; nt++) {
            const int col = ng * 40 + nt * 8 + 2 * tig;
            const float blo = bias_s[col], bhi = bias_s[col + 1];
            float2 v0 = make_float2(acc[m2][nt][0] + blo, acc[m2][nt][1] + bhi);
            *(float2*)(og + (size_t)row0 * NLAT + col) = v0;
            float2 v1 = make_float2(acc[m2][nt][2] + blo, acc[m2][nt][3] + bhi);
            *(float2*)(og + (size_t)(row0 + 8) * NLAT + col) = v1;
        }
    }
}

extern "C" void kernel_launch(void* const* d_in, const int* in_sizes, int n_in,
                              void* d_out, int out_size) {
    const float* spikes = (const float*)d_in[0];
    const float* W_area = (const float*)d_in[1];
    const float* b_area = (const float*)d_in[2];
    const float* U_W    = (const float*)d_in[3];
    const float* U_b    = (const float*)d_in[4];
    const float* V_W    = (const float*)d_in[5];
    const float* V_b    = (const float*)d_in[6];
    const int*   ids    = (const int*)d_in[7];
    float* out = (float*)d_out;

    cudaFuncSetAttribute(main_kernel, cudaFuncAttributeMaxDynamicSharedMemorySize, SMEM_BYTES);

    p1a_kernel<<<160, 256>>>(V_W, U_W, W_area);
    p1b_kernel<<<160, 256>>>(V_W, U_b, V_b, b_area, ids);
    main_kernel<<<dim3(16, 32), 256, SMEM_BYTES>>>(spikes, ids, out);
}

// round 5
// speedup vs baseline: 1.6416x; 1.0256x over previous
#include <cuda_runtime.h>

#define BB 32
#define TT 1024
#define RR 8
#define CC 32
#define NPRD 128
#define RCDIM 256
#define HIDD 1024
#define NLAT 160
#define RKEEP 6
#define KSPLIT 16

// scratch (no allocations allowed)
__device__ float g_M[NLAT * RCDIM];           // M = V_W @ U_W (tf32-rounded)
__device__ float g_Mp[KSPLIT][NLAT * RCDIM];  // K-split partials
__device__ float g_Wtf[RR * CC * NPRD];       // tf32-rounded W_area
__device__ float g_biasb[BB * NLAT];          // per-batch fused bias

__device__ __forceinline__ unsigned f2tf(float x) {
    unsigned r;
    asm("cvt.rna.tf32.f32 %0, %1;" : "=r"(r) : "f"(x));
    return r;
}

__device__ __forceinline__ void mma8(float* c,
                                     unsigned a0, unsigned a1, unsigned a2, unsigned a3,
                                     unsigned b0, unsigned b1) {
    asm volatile(
        "mma.sync.aligned.m16n8k8.row.col.f32.tf32.tf32.f32 "
        "{%0,%1,%2,%3}, {%4,%5,%6,%7}, {%8,%9}, {%0,%1,%2,%3};"
        : "+f"(c[0]), "+f"(c[1]), "+f"(c[2]), "+f"(c[3])
        : "r"(a0), "r"(a1), "r"(a2), "r"(a3), "r"(b0), "r"(b1));
}

__device__ __forceinline__ void cp16(float* dst, const float4* src) {
    unsigned d = (unsigned)__cvta_generic_to_shared(dst);
    asm volatile("cp.async.cg.shared.global [%0], [%1], 16;\n"
                 :: "r"(d), "l"(src) : "memory");
}

// ---------------------------------------------------------------------------
// p1a: M partials. grid = 5(l,32) x 8(c,32) x 16(kc,64) = 640 blocks, 256 thr.
// Per block 32x32 outs, 2x2 per thread, K=64. Also tf32-rounds W_area.
// ---------------------------------------------------------------------------
__global__ void __launch_bounds__(256) p1a_kernel(const float* __restrict__ V_W,
                                                  const float* __restrict__ U_W,
                                                  const float* __restrict__ W_area) {
    __shared__ float Vs[32 * 68];
    __shared__ float Us[64 * 36];
    const int bx = blockIdx.x;
    const int kc = bx & 15;
    const int ct = (bx >> 4) & 7;
    const int lt = bx >> 7;
    const int tid = threadIdx.x;

    // W rounding: 640 blocks x 64 elements = 40960
    if (tid < 64) {
        const int wi = bx * 64 + tid;
        g_Wtf[wi] = __uint_as_float(f2tf(W_area[wi]));
    }

#pragma unroll
    for (int k = 0; k < 2; k++) {          // 32 rows x 16 float4
        const int idx = tid + k * 256;
        const int row = idx >> 4, c4 = idx & 15;
        *(float4*)(Vs + row * 68 + c4 * 4) =
            *(const float4*)(V_W + (size_t)(lt * 32 + row) * HIDD + kc * 64 + c4 * 4);
    }
#pragma unroll
    for (int k = 0; k < 2; k++) {          // 64 rows x 8 float4
        const int idx = tid + k * 256;
        const int row = idx >> 3, c4 = idx & 7;
        *(float4*)(Us + row * 36 + c4 * 4) =
            *(const float4*)(U_W + (size_t)(kc * 64 + row) * RCDIM + ct * 32 + c4 * 4);
    }
    __syncthreads();

    const int ty = tid >> 4, tx = tid & 15;
    float acc[2][2] = {};
#pragma unroll 16
    for (int k = 0; k < 64; k++) {
        const float a0 = Vs[(2 * ty) * 68 + k];
        const float a1 = Vs[(2 * ty + 1) * 68 + k];
        const float2 bv = *(const float2*)(Us + k * 36 + 2 * tx);
        acc[0][0] += a0 * bv.x; acc[0][1] += a0 * bv.y;
        acc[1][0] += a1 * bv.x; acc[1][1] += a1 * bv.y;
    }
#pragma unroll
    for (int rr = 0; rr < 2; rr++) {
        *(float2*)(&g_Mp[kc][(size_t)(lt * 32 + 2 * ty + rr) * RCDIM + ct * 32 + 2 * tx]) =
            make_float2(acc[rr][0], acc[rr][1]);
    }
}

// ---------------------------------------------------------------------------
// p1b: block l: reduce g_Mp -> g_M row l (tf32-rounded); bias2; g_biasb.
// grid 160, 256 threads.
// ---------------------------------------------------------------------------
__global__ void __launch_bounds__(256) p1b_kernel(const float* __restrict__ V_W,
                                                  const float* __restrict__ U_b,
                                                  const float* __restrict__ V_b,
                                                  const float* __restrict__ b_area,
                                                  const int* __restrict__ ids) {
    __shared__ float Ms[RCDIM];
    __shared__ float ba_s[RCDIM];
    __shared__ float red[256];
    const int l = blockIdx.x, t = threadIdx.x;

    float s = 0.f;
#pragma unroll
    for (int p = 0; p < KSPLIT; p++) s += g_Mp[p][(size_t)l * RCDIM + t];
    const float mv = __uint_as_float(f2tf(s));
    g_M[(size_t)l * RCDIM + t] = mv;
    Ms[t] = mv;
    ba_s[t] = b_area[t];

    float s2 = 0.f;
#pragma unroll
    for (int i = 0; i < 4; i++)
        s2 += V_W[(size_t)l * HIDD + t + i * 256] * U_b[t + i * 256];
    red[t] = s2;
    __syncthreads();
    for (int st = 128; st > 0; st >>= 1) {
        if (t < st) red[t] += red[t + st];
        __syncthreads();
    }
    const float bias2 = red[0] + V_b[l];

    if (t < BB) {
        const int b = t;
        float s3 = bias2;
#pragma unroll
        for (int j = 0; j < RKEEP; j++) {
            const int r = ids[b * RR + j];
#pragma unroll
            for (int c = 0; c < CC; c++) s3 += Ms[r * CC + c] * ba_s[r * CC + c];
        }
        g_biasb[b * NLAT + l] = s3;
    }
}

// ---------------------------------------------------------------------------
// Main fused kernel. grid = (16 t-tiles x 32 batches), 256 threads, 2 CTAs/SM.
// Implicit k-permutation: MMA physical col tig -> logical 2*tig, tig+4 -> 2*tig+1,
// applied consistently to A and B => all fragment accesses are float2 (LDS.64).
// Smem swizzle at float2 granularity:
//   x/w (128-col rows): float off = row*128 + 2*((4ks+tig) ^ (4*(row&7)))
//   m/h ( 32-col rows): float off = row*32  + 2*((4ks+tig) ^ (4*(row&3)))
// ---------------------------------------------------------------------------
constexpr int TILE_T = 64;
constexpr int XTILE = TILE_T * 128;                 // 8192
constexpr int W_OFF = 2 * XTILE;                    // 16384, 32*128 = 4096
constexpr int M_OFF = W_OFF + 32 * 128;             // 20480, 160*32 = 5120
constexpr int H_OFF = M_OFF + NLAT * 32;            // 25600, 64*32 = 2048
constexpr int B_OFF = H_OFF + TILE_T * 32;          // 27648
constexpr int SMEM_FLOATS = B_OFF + NLAT;           // 27808
constexpr int SMEM_BYTES = SMEM_FLOATS * 4;         // 111,232 B

__global__ void __launch_bounds__(256, 2) main_kernel(const float* __restrict__ spikes,
                                                      const int* __restrict__ ids,
                                                      float* __restrict__ out) {
    extern __shared__ float sm[];
    float* xs = sm;
    float* ws = sm + W_OFF;
    float* ms = sm + M_OFF;
    float* hs = sm + H_OFF;
    float* bias_s = sm + B_OFF;

    const int tid = threadIdx.x;
    const int wid = tid >> 5, lane = tid & 31;
    const int g = lane >> 2, tig = lane & 3;
    const int b = blockIdx.y, t0 = blockIdx.x * TILE_T;

    if (tid < NLAT) bias_s[tid] = g_biasb[b * NLAT + tid];

    const size_t xbase = ((size_t)b * TT + t0) * (size_t)(RR * NPRD);

    // stage1: 4 m-tiles(16 rows) x 2 n-halves(16 cols); stage2: 2 mg x 4 ng(40 cols)
    const int mt = wid >> 1, nh = wid & 1;
    const int mg = wid >> 2, ng = wid & 3;

    int kept[RKEEP];
#pragma unroll
    for (int j = 0; j < RKEEP; j++) kept[j] = __ldg(ids + b * RR + j);

    float acc[2][5][4];
#pragma unroll
    for (int a = 0; a < 2; a++)
#pragma unroll
        for (int n = 0; n < 5; n++)
#pragma unroll
            for (int q = 0; q < 4; q++) acc[a][n][q] = 0.f;

    auto prefetch_xw = [&](int buf, int r) {
        const float4* xg = (const float4*)(spikes + xbase + (size_t)r * NPRD);
        float* xd = xs + buf * XTILE;
#pragma unroll
        for (int k = 0; k < 8; k++) {            // 64 rows x 32 float4
            const int idx = tid + k * 256;
            const int row = idx >> 5, c4 = idx & 31;
            cp16(xd + row * 128 + 2 * ((2 * c4) ^ (4 * (row & 7))),
                 xg + (size_t)row * 256 + c4);
        }
        const float4* wg = (const float4*)(g_Wtf + (size_t)r * CC * NPRD);
#pragma unroll
        for (int k = 0; k < 4; k++) {            // 32 rows x 32 float4
            const int idx = tid + k * 256;
            const int row = idx >> 5, c4 = idx & 31;
            cp16(ws + row * 128 + 2 * ((2 * c4) ^ (4 * (row & 7))),
                 wg + row * 32 + c4);
        }
    };
    auto prefetch_m = [&](int r) {
        const float* Mg = g_M + (size_t)r * CC;
#pragma unroll
        for (int k = 0; k < 5; k++) {            // 160 rows x 8 float4
            const int idx = tid + k * 256;
            const int row = idx >> 3, c4 = idx & 7;
            cp16(ms + row * 32 + 2 * ((2 * c4) ^ (4 * (row & 3))),
                 (const float4*)(Mg + (size_t)row * RCDIM) + c4);
        }
    };

    prefetch_xw(0, kept[0]);
    asm volatile("cp.async.commit_group;\n" ::: "memory");
    prefetch_m(kept[0]);
    asm volatile("cp.async.commit_group;\n" ::: "memory");

    for (int j = 0; j < RKEEP; j++) {
        const int cur = j & 1;

        // wait xw_j (M group may still be in flight)
        asm volatile("cp.async.wait_group 1;\n" ::: "memory");
        __syncthreads();

        // ---- stage 1: h(64x32) = x(64x128) @ W^T, K=128, 4 acc chains ----
        float ha[2][4] = {}, hb[2][4] = {};
        {
            // base pointers include row*128 + 2*tig; per ks add 8*(ks^g)
            const float* xr0 = xs + cur * XTILE + (mt * 16 + g) * 128 + 2 * tig;
            const float* wr0 = ws + (nh * 16 + g) * 128 + 2 * tig;
#pragma unroll
            for (int ks = 0; ks < 16; ks++) {
                const int ko = 8 * (ks ^ g);
                const float2 x0 = *(const float2*)(xr0 + ko);
                const float2 x1 = *(const float2*)(xr0 + 1024 + ko);
                const unsigned a0 = f2tf(x0.x);
                const unsigned a2 = f2tf(x0.y);
                const unsigned a1 = f2tf(x1.x);
                const unsigned a3 = f2tf(x1.y);
                const float2 w0 = *(const float2*)(wr0 + ko);
                const float2 w1 = *(const float2*)(wr0 + 1024 + ko);
                float* h0 = (ks & 1) ? hb[0] : ha[0];
                float* h1 = (ks & 1) ? hb[1] : ha[1];
                mma8(h0, a0, a1, a2, a3, __float_as_uint(w0.x), __float_as_uint(w0.y));
                mma8(h1, a0, a1, a2, a3, __float_as_uint(w1.x), __float_as_uint(w1.y));
            }
        }
        // wait M_j, then publish h (tf32-rounded, float2 stores)
        asm volatile("cp.async.wait_group 0;\n" ::: "memory");
        {
            const int g3 = 4 * (g & 3);
#pragma unroll
            for (int nt = 0; nt < 2; nt++) {
                const int f = nh * 8 + nt * 4 + tig;
                float* hp0 = hs + (mt * 16 + g) * 32 + 2 * (f ^ g3);
                *(float2*)hp0 = make_float2(__uint_as_float(f2tf(ha[nt][0] + hb[nt][0])),
                                            __uint_as_float(f2tf(ha[nt][1] + hb[nt][1])));
                float* hp1 = hs + (mt * 16 + g + 8) * 32 + 2 * (f ^ g3);
                *(float2*)hp1 = make_float2(__uint_as_float(f2tf(ha[nt][2] + hb[nt][2])),
                                            __uint_as_float(f2tf(ha[nt][3] + hb[nt][3])));
            }
        }
        __syncthreads();

        // x_j / w_j dead: start next xw load (overlaps stage 2)
        if (j + 1 < RKEEP) {
            prefetch_xw(cur ^ 1, kept[j + 1]);
            asm volatile("cp.async.commit_group;\n" ::: "memory");
        }

        // ---- stage 2: out(64x160) += h @ M_r^T, K=32 ----
        {
            const int g3 = 4 * (g & 3);
#pragma unroll
            for (int ks = 0; ks < 4; ks++) {
                const int fo = 2 * ((4 * ks + tig) ^ g3);
                unsigned A[2][4];
#pragma unroll
                for (int m2 = 0; m2 < 2; m2++) {
                    const int row0 = mg * 32 + m2 * 16 + g;
                    const float2 h0 = *(const float2*)(hs + row0 * 32 + fo);
                    const float2 h1 = *(const float2*)(hs + (row0 + 8) * 32 + fo);
                    A[m2][0] = __float_as_uint(h0.x);
                    A[m2][2] = __float_as_uint(h0.y);
                    A[m2][1] = __float_as_uint(h1.x);
                    A[m2][3] = __float_as_uint(h1.y);
                }
#pragma unroll
                for (int nt = 0; nt < 5; nt++) {
                    const float2 bm = *(const float2*)(ms + (ng * 40 + nt * 8 + g) * 32 + fo);
                    const unsigned b0 = __float_as_uint(bm.x);
                    const unsigned b1 = __float_as_uint(bm.y);
                    mma8(acc[0][nt], A[0][0], A[0][1], A[0][2], A[0][3], b0, b1);
                    mma8(acc[1][nt], A[1][0], A[1][1], A[1][2], A[1][3], b0, b1);
                }
            }
        }
        __syncthreads();

        // M_j dead: start next M load (overlaps next stage 1)
        if (j + 1 < RKEEP) {
            prefetch_m(kept[j + 1]);
            asm volatile("cp.async.commit_group;\n" ::: "memory");
        }
    }

    // ---- epilogue ----
    float* og = out + ((size_t)b * TT + t0) * NLAT;
#pragma unroll
    for (int m2 = 0; m2 < 2; m2++) {
        const int row0 = mg * 32 + m2 * 16 + g;
#pragma unroll
        for (int nt = 0; nt < 5; nt++) {
            const int col = ng * 40 + nt * 8 + 2 * tig;
            const float blo = bias_s[col], bhi = bias_s[col + 1];
            float2 v0 = make_float2(acc[m2][nt][0] + blo, acc[m2][nt][1] + bhi);
            *(float2*)(og + (size_t)row0 * NLAT + col) = v0;
            float2 v1 = make_float2(acc[m2][nt][2] + blo, acc[m2][nt][3] + bhi);
            *(float2*)(og + (size_t)(row0 + 8) * NLAT + col) = v1;
        }
    }
}

extern "C" void kernel_launch(void* const* d_in, const int* in_sizes, int n_in,
                              void* d_out, int out_size) {
    const float* spikes = (const float*)d_in[0];
    const float* W_area = (const float*)d_in[1];
    const float* b_area = (const float*)d_in[2];
    const float* U_W    = (const float*)d_in[3];
    const float* U_b    = (const float*)d_in[4];
    const float* V_W    = (const float*)d_in[5];
    const float* V_b    = (const float*)d_in[6];
    const int*   ids    = (const int*)d_in[7];
    float* out = (float*)d_out;

    cudaFuncSetAttribute(main_kernel, cudaFuncAttributeMaxDynamicSharedMemorySize, SMEM_BYTES);

    p1a_kernel<<<640, 256>>>(V_W, U_W, W_area);
    p1b_kernel<<<160, 256>>>(V_W, U_b, V_b, b_area, ids);
    main_kernel<<<dim3(16, 32), 256, SMEM_BYTES>>>(spikes, ids, out);
}

// round 8
// speedup vs baseline: 2.0414x; 1.2436x over previous
#include <cuda_runtime.h>
#include <cuda_fp16.h>
#include <cstdint>

#define BB 32
#define TT 1024
#define RR 8
#define CC 32
#define NPRD 128
#define RCDIM 256
#define HIDD 1024
#define NLAT 160
#define RKEEP 6
#define KSPLIT 16

// scratch (no allocations allowed)
__device__ float  g_Mp[KSPLIT][NLAT * RCDIM];  // M K-split partials (f32)
__device__ __half g_M16[NLAT * RCDIM];         // M in fp16 (160 x 256)
__device__ __half g_W16[RR * CC * NPRD];       // W_area in fp16 (8 x 32 x 128)
__device__ float  g_biasb[BB * NLAT];          // per-batch fused bias

__device__ __forceinline__ unsigned cvt2(float hi, float lo) {
    unsigned d;
    asm("cvt.rn.f16x2.f32 %0, %1, %2;" : "=r"(d) : "f"(hi), "f"(lo));
    return d;
}

__device__ __forceinline__ void mma16(float* c,
                                      unsigned a0, unsigned a1, unsigned a2, unsigned a3,
                                      unsigned b0, unsigned b1) {
    asm volatile(
        "mma.sync.aligned.m16n8k16.row.col.f32.f16.f16.f32 "
        "{%0,%1,%2,%3}, {%4,%5,%6,%7}, {%8,%9}, {%0,%1,%2,%3};"
        : "+f"(c[0]), "+f"(c[1]), "+f"(c[2]), "+f"(c[3])
        : "r"(a0), "r"(a1), "r"(a2), "r"(a3), "r"(b0), "r"(b1));
}

__device__ __forceinline__ void cp16(void* dst, const void* src) {
    unsigned d = (unsigned)__cvta_generic_to_shared(dst);
    asm volatile("cp.async.cg.shared.global [%0], [%1], 16;\n"
                 :: "r"(d), "l"(src) : "memory");
}
__device__ __forceinline__ void cp8(void* dst, const void* src) {
    unsigned d = (unsigned)__cvta_generic_to_shared(dst);
    asm volatile("cp.async.ca.shared.global [%0], [%1], 8;\n"
                 :: "r"(d), "l"(src) : "memory");
}
#define CP_COMMIT() asm volatile("cp.async.commit_group;\n" ::: "memory")
#define CP_WAIT0()  asm volatile("cp.async.wait_group 0;\n" ::: "memory")
#define CP_WAIT1()  asm volatile("cp.async.wait_group 1;\n" ::: "memory")

// ---------------------------------------------------------------------------
// p1a: M partials. grid = 5(l,32) x 4(c,64) x 16(kc,64) = 320 blocks, 256 thr.
// Thread tile 2l x 4c. Also converts W_area -> g_W16 (fp16).
// ---------------------------------------------------------------------------
__global__ void __launch_bounds__(256) p1a_kernel(const float* __restrict__ V_W,
                                                  const float* __restrict__ U_W,
                                                  const float* __restrict__ W_area) {
    __shared__ float Vs[32 * 68];
    __shared__ float Us[64 * 68];
    const int bx = blockIdx.x;
    const int kc = bx & 15;
    const int ct = (bx >> 4) & 3;
    const int lt = bx >> 6;
    const int tid = threadIdx.x;

    // W conversion: 320 blocks x 128 elements = 40960
    if (tid < 128) {
        const int wi = bx * 128 + tid;
        g_W16[wi] = __float2half_rn(W_area[wi]);
    }

#pragma unroll
    for (int k = 0; k < 2; k++) {          // 32 rows x 16 float4
        const int idx = tid + k * 256;
        const int row = idx >> 4, c4 = idx & 15;
        *(float4*)(Vs + row * 68 + c4 * 4) =
            *(const float4*)(V_W + (size_t)(lt * 32 + row) * HIDD + kc * 64 + c4 * 4);
    }
#pragma unroll
    for (int k = 0; k < 4; k++) {          // 64 rows x 16 float4
        const int idx = tid + k * 256;
        const int row = idx >> 4, c4 = idx & 15;
        *(float4*)(Us + row * 68 + c4 * 4) =
            *(const float4*)(U_W + (size_t)(kc * 64 + row) * RCDIM + ct * 64 + c4 * 4);
    }
    __syncthreads();

    const int ty = tid >> 4, tx = tid & 15;
    float acc[2][4] = {};
#pragma unroll 16
    for (int k = 0; k < 64; k++) {
        const float a0 = Vs[(2 * ty) * 68 + k];
        const float a1 = Vs[(2 * ty + 1) * 68 + k];
        const float4 bv = *(const float4*)(Us + k * 68 + 4 * tx);
        acc[0][0] += a0 * bv.x; acc[0][1] += a0 * bv.y;
        acc[0][2] += a0 * bv.z; acc[0][3] += a0 * bv.w;
        acc[1][0] += a1 * bv.x; acc[1][1] += a1 * bv.y;
        acc[1][2] += a1 * bv.z; acc[1][3] += a1 * bv.w;
    }
#pragma unroll
    for (int rr = 0; rr < 2; rr++) {
        *(float4*)(&g_Mp[kc][(size_t)(lt * 32 + 2 * ty + rr) * RCDIM + ct * 64 + 4 * tx]) =
            make_float4(acc[rr][0], acc[rr][1], acc[rr][2], acc[rr][3]);
    }
}

// ---------------------------------------------------------------------------
// p1bc: block l: reduce g_Mp -> M row l; write g_M16 (fp16); bias2; g_biasb.
// grid 160, 256 threads.
// ---------------------------------------------------------------------------
__global__ void __launch_bounds__(256) p1bc_kernel(const float* __restrict__ V_W,
                                                   const float* __restrict__ U_b,
                                                   const float* __restrict__ V_b,
                                                   const float* __restrict__ b_area,
                                                   const int* __restrict__ ids) {
    __shared__ float Ms[RCDIM];
    __shared__ float ba_s[RCDIM];
    __shared__ float red[256];
    const int l = blockIdx.x, t = threadIdx.x;

    float s = 0.f;
#pragma unroll
    for (int p = 0; p < KSPLIT; p++) s += g_Mp[p][(size_t)l * RCDIM + t];
    g_M16[(size_t)l * RCDIM + t] = __float2half_rn(s);
    Ms[t] = s;
    ba_s[t] = b_area[t];

    float s2 = 0.f;
#pragma unroll
    for (int i = 0; i < 4; i++)
        s2 += V_W[(size_t)l * HIDD + t + i * 256] * U_b[t + i * 256];
    red[t] = s2;
    __syncthreads();
    for (int st = 128; st > 0; st >>= 1) {
        if (t < st) red[t] += red[t + st];
        __syncthreads();
    }
    const float bias2 = red[0] + V_b[l];

    if (t < BB) {
        const int b = t;
        float s3 = bias2;
#pragma unroll
        for (int j = 0; j < RKEEP; j++) {
            const int r = ids[b * RR + j];
#pragma unroll
            for (int c = 0; c < CC; c++) s3 += Ms[r * CC + c] * ba_s[r * CC + c];
        }
        g_biasb[b * NLAT + l] = s3;
    }
}

// ---------------------------------------------------------------------------
// Main fused kernel (fp16 mma, f32 accumulate). grid = (16 t-tiles x 32 b),
// 256 threads, 2 CTAs/SM. Per region: merged span [stage2(j); stage1(j+1)].
// ---------------------------------------------------------------------------
constexpr int XOFF_F = 0;            // float index
constexpr int XBUF_F = 64 * 128;     // 8192
constexpr int WOFF_U = 16384;        // u32 index (byte 65536)
constexpr int WBUF_U = 32 * 64;      // 2048
constexpr int MOFF_U = WOFF_U + 2 * WBUF_U;       // 20480
constexpr int MBUF_U = 160 * 16;                  // 2560
constexpr int HOFF_U = MOFF_U + 2 * MBUF_U;       // 25600
constexpr int BOFF_F = HOFF_U + 64 * 16;          // 26624 (float idx == u32 idx)
constexpr int SMEM_BYTES = (BOFF_F + NLAT) * 4;   // 107,136

__global__ void __launch_bounds__(256, 2) main_kernel(const float* __restrict__ spikes,
                                                      const int* __restrict__ ids,
                                                      float* __restrict__ out) {
    extern __shared__ float sm[];
    float* xsf = sm + XOFF_F;
    unsigned* wu = (unsigned*)sm + WOFF_U;
    unsigned* mu = (unsigned*)sm + MOFF_U;
    unsigned* hu = (unsigned*)sm + HOFF_U;
    float* bias_s = sm + BOFF_F;

    const int tid = threadIdx.x;
    const int wid = tid >> 5, lane = tid & 31;
    const int g = lane >> 2, tig = lane & 3;
    const int b = blockIdx.y, t0 = blockIdx.x * 64;

    if (tid < NLAT) bias_s[tid] = g_biasb[b * NLAT + tid];

    // stage1: 4 m-tiles(16 rows) x 2 n-halves(16 cols); stage2: 2 mg x 4 ng(40 cols)
    const int mt = wid >> 1, nh = wid & 1;
    const int mg = wid >> 2, ng = wid & 3;

    int kept[RKEEP];
#pragma unroll
    for (int j = 0; j < RKEEP; j++) kept[j] = __ldg(ids + b * RR + j);

    const float* xg_base = spikes + ((size_t)(b * TT + t0)) * (RR * NPRD);

    auto load_x = [&](int buf, int r) {
        const float* xg = xg_base + r * NPRD;
        float* xd = xsf + (buf & 1) * XBUF_F;
#pragma unroll
        for (int k = 0; k < 8; k++) {            // 64 rows x 32 float4
            const int idx = tid + k * 256;
            const int row = idx >> 5, c4 = idx & 31;
            cp16(xd + row * 128 + 2 * ((2 * c4) ^ (4 * (row & 7))),
                 xg + (size_t)row * (RR * NPRD) + 4 * c4);
        }
    };
    auto load_w = [&](int buf, int r) {
        unsigned* wd = wu + (buf & 1) * WBUF_U;
#pragma unroll
        for (int k = 0; k < 2; k++) {            // 32 rows x 16 uint4
            const int idx = tid + k * 256;
            const int row = idx >> 4, c4 = idx & 15;
            cp16(wd + row * 64 + ((4 * c4) ^ (4 * (row & 7))),
                 (const char*)g_W16 + (size_t)r * 8192 + row * 256 + 16 * c4);
        }
    };
    auto load_m = [&](int buf, int r) {
        unsigned* md = mu + (buf & 1) * MBUF_U;
#pragma unroll
        for (int k = 0; k < 5; k++) {            // 160 rows x 8 x 8B
            const int idx = tid + k * 256;
            const int row = idx >> 3, cp = idx & 7;
            cp8(md + row * 16 + ((2 * cp) ^ (2 * (row & 7))),
                (const char*)g_M16 + (size_t)row * 512 + r * 64 + 8 * cp);
        }
    };

    float acc[2][5][4];
#pragma unroll
    for (int a = 0; a < 2; a++)
#pragma unroll
        for (int n = 0; n < 5; n++)
#pragma unroll
            for (int q = 0; q < 4; q++) acc[a][n][q] = 0.f;

    float hacc[2][4];

    const int sw4 = 4 * g;   // x / w swizzle constant (row&7 == g for all frag rows)
    const int sw2 = 2 * g;   // m / h swizzle constant

    auto stage1 = [&](int jj) {
        const int cur = jj & 1;
#pragma unroll
        for (int n = 0; n < 2; n++)
#pragma unroll
            for (int q = 0; q < 4; q++) hacc[n][q] = 0.f;
        const float* xr = xsf + cur * XBUF_F + (mt * 16 + g) * 128;
        const unsigned* wr0 = wu + cur * WBUF_U + (nh * 16 + g) * 64;
        const unsigned* wr1 = wr0 + 8 * 64;
#pragma unroll
        for (int ks = 0; ks < 8; ks++) {
            const int p0 = 8 * ks + tig;
            const int o0 = p0 ^ sw4;
            const int o1 = (p0 + 4) ^ sw4;
            const float2 xa0 = *(const float2*)(xr + 2 * o0);
            const float2 xa2 = *(const float2*)(xr + 2 * o1);
            const float2 xb0 = *(const float2*)(xr + 1024 + 2 * o0);
            const float2 xb2 = *(const float2*)(xr + 1024 + 2 * o1);
            const unsigned a0 = cvt2(xa0.y, xa0.x);
            const unsigned a2 = cvt2(xa2.y, xa2.x);
            const unsigned a1 = cvt2(xb0.y, xb0.x);
            const unsigned a3 = cvt2(xb2.y, xb2.x);
            mma16(hacc[0], a0, a1, a2, a3, wr0[o0], wr0[o1]);
            mma16(hacc[1], a0, a1, a2, a3, wr1[o0], wr1[o1]);
        }
    };
    auto publish_h = [&]() {
#pragma unroll
        for (int nt = 0; nt < 2; nt++) {
            const int q = nh * 8 + nt * 4 + tig;
            const int row0 = mt * 16 + g;
            hu[row0 * 16 + (q ^ sw2)] = cvt2(hacc[nt][1], hacc[nt][0]);
            hu[(row0 + 8) * 16 + (q ^ sw2)] = cvt2(hacc[nt][3], hacc[nt][2]);
        }
    };
    auto stage2 = [&](int j) {
        const unsigned* mb = mu + (j & 1) * MBUF_U;
#pragma unroll
        for (int ks = 0; ks < 2; ks++) {
            const int p0 = 8 * ks + tig;
            const int o0 = p0 ^ sw2;
            const int o1 = (p0 + 4) ^ sw2;
            unsigned A[2][4];
#pragma unroll
            for (int m2 = 0; m2 < 2; m2++) {
                const int row0 = mg * 32 + m2 * 16 + g;
                A[m2][0] = hu[row0 * 16 + o0];
                A[m2][2] = hu[row0 * 16 + o1];
                A[m2][1] = hu[(row0 + 8) * 16 + o0];
                A[m2][3] = hu[(row0 + 8) * 16 + o1];
            }
#pragma unroll
            for (int nt = 0; nt < 5; nt++) {
                const unsigned* mr = mb + (ng * 40 + nt * 8 + g) * 16;
                const unsigned b0 = mr[o0], b1 = mr[o1];
                mma16(acc[0][nt], A[0][0], A[0][1], A[0][2], A[0][3], b0, b1);
                mma16(acc[1][nt], A[1][0], A[1][1], A[1][2], A[1][3], b0, b1);
            }
        }
    };

    // prologue
    load_x(0, kept[0]); load_w(0, kept[0]); CP_COMMIT();                      // GA
    load_m(0, kept[0]); load_x(1, kept[1]); load_w(1, kept[1]); CP_COMMIT();  // GB
    CP_WAIT1();
    __syncthreads();
    stage1(0);
    publish_h();

    for (int j = 0; j < RKEEP; j++) {
        CP_WAIT0();
        __syncthreads();
        // issue loads for span j+1 (after sync: prior readers of these bufs are done)
        if (j + 1 < RKEEP) {
            load_m((j + 1) & 1, kept[j + 1]);
            if (j + 2 < RKEEP) {
                load_x((j + 2) & 1, kept[j + 2]);
                load_w((j + 2) & 1, kept[j + 2]);
            }
            CP_COMMIT();
        }
        stage2(j);                 // reads h(j), m(j)
        if (j + 1 < RKEEP) {
            stage1(j + 1);         // reads x(j+1), w(j+1) -> hacc regs
            __syncthreads();       // all warps done with h(j)
            publish_h();           // write h(j+1)
        }
    }

    // ---- epilogue ----
    float* og = out + ((size_t)(b * TT + t0)) * NLAT;
#pragma unroll
    for (int m2 = 0; m2 < 2; m2++) {
        const int row0 = mg * 32 + m2 * 16 + g;
#pragma unroll
        for (int nt = 0; nt < 5; nt++) {
            const int col = ng * 40 + nt * 8 + 2 * tig;
            const float blo = bias_s[col], bhi = bias_s[col + 1];
            float2 v0 = make_float2(acc[m2][nt][0] + blo, acc[m2][nt][1] + bhi);
            *(float2*)(og + (size_t)row0 * NLAT + col) = v0;
            float2 v1 = make_float2(acc[m2][nt][2] + blo, acc[m2][nt][3] + bhi);
            *(float2*)(og + (size_t)(row0 + 8) * NLAT + col) = v1;
        }
    }
}

extern "C" void kernel_launch(void* const* d_in, const int* in_sizes, int n_in,
                              void* d_out, int out_size) {
    const float* spikes = (const float*)d_in[0];
    const float* W_area = (const float*)d_in[1];
    const float* b_area = (const float*)d_in[2];
    const float* U_W    = (const float*)d_in[3];
    const float* U_b    = (const float*)d_in[4];
    const float* V_W    = (const float*)d_in[5];
    const float* V_b    = (const float*)d_in[6];
    const int*   ids    = (const int*)d_in[7];
    float* out = (float*)d_out;

    cudaFuncSetAttribute(main_kernel, cudaFuncAttributeMaxDynamicSharedMemorySize, SMEM_BYTES);

    p1a_kernel<<<320, 256>>>(V_W, U_W, W_area);
    p1bc_kernel<<<160, 256>>>(V_W, U_b, V_b, b_area, ids);
    main_kernel<<<dim3(16, 32), 256, SMEM_BYTES>>>(spikes, ids, out);
}